// round 5
// baseline (speedup 1.0000x reference)
#include <cuda_runtime.h>

#define B_   4096
#define T_   64
#define OBS_ 64
#define H_   64
#define A_   8
#define S_   201
#define G_   16
#define NTHR 128
#define ST   20     // transposed-buffer stride (mult of 4 for LDS.128 alignment)

typedef unsigned long long u64;
typedef unsigned int u32;

__device__ __forceinline__ u64 fma2(u64 a, u64 b, u64 c) {
    u64 d;
    asm("fma.rn.f32x2 %0, %1, %2, %3;" : "=l"(d) : "l"(a), "l"(b), "l"(c));
    return d;
}
__device__ __forceinline__ u64 pack2(float x, float y) {
    u64 d;
    asm("mov.b64 %0, {%1, %2};" : "=l"(d) : "r"(__float_as_uint(x)), "r"(__float_as_uint(y)));
    return d;
}
__device__ __forceinline__ float2 unpack2(u64 a) {
    u32 lo, hi;
    asm("mov.b64 {%0, %1}, %2;" : "=r"(lo), "=r"(hi) : "l"(a));
    float2 r; r.x = __uint_as_float(lo); r.y = __uint_as_float(hi);
    return r;
}

// XLA/Eigen f32 fast-tanh clone (matches the JAX reference's lowering) —
// DO NOT TOUCH: decision-critical arithmetic, validated in R3.
__device__ __forceinline__ float tanh_xla(float x) {
    float xc = fminf(fmaxf(x, -7.90531110763549805f), 7.90531110763549805f);
    float x2 = xc * xc;
    float p = -2.76076847742355e-16f;
    p = __fmaf_rn(p, x2, 2.00018790482477e-13f);
    p = __fmaf_rn(p, x2, -8.60467152213735e-11f);
    p = __fmaf_rn(p, x2, 5.12229709037114e-08f);
    p = __fmaf_rn(p, x2, 1.48572235717979e-05f);
    p = __fmaf_rn(p, x2, 6.37261928875436e-04f);
    p = __fmaf_rn(p, x2, 4.89352455891786e-03f);
    float num = xc * p;
    float q = 1.19825839466702e-06f;
    q = __fmaf_rn(q, x2, 1.18534705686654e-04f);
    q = __fmaf_rn(q, x2, 2.26843463243900e-03f);
    q = __fmaf_rn(q, x2, 4.89352518554385e-03f);
    float r = __fdiv_rn(num, q);
    return (fabsf(x) < 0.0004f) ? x : r;
}

// output layout (flattened tuple, float32):
#define OFF_VAL ((size_t)B_ * T_ * A_)
#define OFF_STK (OFF_VAL + (size_t)T_ * B_)
#define OFF_PTR (OFF_STK + (size_t)B_ * S_ * H_)

// p scratch for deferred policy/value heads: [B][T][H]
__device__ float g_P[(size_t)B_ * T_ * H_];

// shared memory layout (float offsets)
#define SM_W1T   0                        // 128*64
#define SM_W2T   (SM_W1T + 8192)          // 64*64
#define SM_WST   (SM_W2T + 4096)          // 64*3
#define SM_B1    (SM_WST + 192)           // 64
#define SM_B2    (SM_B1 + 64)             // 64
#define SM_BS    (SM_B2 + 64)             // 4 (3 used)
#define SM_IN    (SM_BS + 4)              // 128*ST
#define SM_HT    (SM_IN + 128 * ST)       // 64*ST
#define SM_PT    (SM_HT + 64 * ST)        // 64*ST
#define SM_LS    (SM_PT + 64 * ST)        // 16*4
#define SM_INTS  (SM_LS + 64)             // ptrS(16) + wbits(112)
#define SMEM_FLOATS (SM_INTS + 128)
#define SMEM_BYTES  (SMEM_FLOATS * 4)

__global__ void __launch_bounds__(NTHR, 2) stacknet_scan(
    const float* __restrict__ x,   const float* __restrict__ stack_in,
    const int*   __restrict__ ptr_in,
    const float* __restrict__ W1,  const float* __restrict__ b1,
    const float* __restrict__ W2,  const float* __restrict__ b2,
    const float* __restrict__ Ws,  const float* __restrict__ bsv,
    float* __restrict__ out)
{
    extern __shared__ float sm[];
    float* W1t = sm + SM_W1T;
    float* W2t = sm + SM_W2T;
    float* Wst = sm + SM_WST;
    float* b1s = sm + SM_B1;
    float* b2s = sm + SM_B2;
    float* bss = sm + SM_BS;
    float* InT = sm + SM_IN;      // [128][ST] concat(x_t, top), transposed
    float* Ht  = sm + SM_HT;      // [64][ST]
    float* Pt  = sm + SM_PT;      // [64][ST]
    float* Ls  = sm + SM_LS;      // [16][4]
    int*   ptrS  = (int*)(sm + SM_INTS);
    u32*   wbits = (u32*)(ptrS + 16);   // [16][7]

    const int tid  = threadIdx.x;
    const int base = blockIdx.x * G_;

    for (int i = tid; i < 8192; i += NTHR) { int j = i >> 7, k = i & 127; W1t[k * 64 + j] = W1[i]; }
    for (int i = tid; i < 4096; i += NTHR) { int j = i >> 6, k = i & 63;  W2t[k * 64 + j] = W2[i]; }
    for (int i = tid; i < 192;  i += NTHR) { int h = i >> 6, k = i & 63;  Wst[k * 3 + h] = Ws[i]; }
    if (tid < 64) { b1s[tid] = b1[tid]; b2s[tid] = b2[tid]; }
    if (tid < 3)  bss[tid] = bsv[tid];
    for (int i = tid; i < G_ * 7; i += NTHR) wbits[i] = 0;
    if (tid < G_) ptrS[tid] = ptr_in[base + tid];
    __syncthreads();

    const int q = tid & 3, c = tid >> 2;    // compute map: rows 4q..4q+3, cols 2c,2c+1
    const int e = tid >> 3, seg = tid & 7;  // IO map: element e, features seg+8i

    const size_t xrow  = (size_t)(base + e) * T_ * OBS_;
    const size_t srow  = (size_t)(base + e) * S_;
    float*       ostk  = out + OFF_STK;

    float xs[8], cs[8], pcm[8], pcp[8];
    {
        int p0 = ptrS[e];
        #pragma unroll
        for (int i = 0; i < 8; ++i) {
            int f = seg + 8 * i;
            xs[i] = x[xrow + f];
            cs[i] = stack_in[(srow + p0) * H_ + f];
            InT[f * ST + e]        = xs[i];
            InT[(64 + f) * ST + e] = cs[i];
        }
    }

    for (int t = 0; t < T_; ++t) {
        __syncthreads();   // InT ready (also orders prev push STG / wbits)

        // --- prefetches (hidden under W1) ---
        const int p = ptrS[e];
        if (t + 1 < T_) {
            const int rm = p > 0 ? p - 1 : 0;
            const int rp = p + 1;
            const float* bm = ((wbits[e * 7 + (rm >> 5)] >> (rm & 31)) & 1u) ? ostk : stack_in;
            const float* bq = ((wbits[e * 7 + (rp >> 5)] >> (rp & 31)) & 1u) ? ostk : stack_in;
            #pragma unroll
            for (int i = 0; i < 8; ++i) {
                int f = seg + 8 * i;
                xs[i]  = x[xrow + (size_t)(t + 1) * OBS_ + f];
                pcm[i] = bm[(srow + rm) * H_ + f];
                pcp[i] = bq[(srow + rp) * H_ + f];
            }
        }

        // --- W1: [16x128]@[128x64], 4x2 tile, f32x2 along rows ---
        u64 a00 = 0ull, a01 = 0ull, a10 = 0ull, a11 = 0ull;
        #pragma unroll 8
        for (int k = 0; k < 128; ++k) {
            float4 f4 = *(const float4*)&InT[k * ST + 4 * q];
            u64 in01 = pack2(f4.x, f4.y), in23 = pack2(f4.z, f4.w);
            float2 w = *(const float2*)&W1t[k * 64 + 2 * c];
            u64 w0 = pack2(w.x, w.x), w1 = pack2(w.y, w.y);
            a00 = fma2(in01, w0, a00); a01 = fma2(in01, w1, a01);
            a10 = fma2(in23, w0, a10); a11 = fma2(in23, w1, a11);
        }
        {
            float2 v00 = unpack2(a00), v01 = unpack2(a01), v10 = unpack2(a10), v11 = unpack2(a11);
            int j0 = 2 * c, g0 = 4 * q;
            Ht[j0 * ST + g0]           = tanh_xla(v00.x + b1s[j0]);
            Ht[j0 * ST + g0 + 1]       = tanh_xla(v00.y + b1s[j0]);
            Ht[(j0 + 1) * ST + g0]     = tanh_xla(v01.x + b1s[j0 + 1]);
            Ht[(j0 + 1) * ST + g0 + 1] = tanh_xla(v01.y + b1s[j0 + 1]);
            Ht[j0 * ST + g0 + 2]       = tanh_xla(v10.x + b1s[j0]);
            Ht[j0 * ST + g0 + 3]       = tanh_xla(v10.y + b1s[j0]);
            Ht[(j0 + 1) * ST + g0 + 2] = tanh_xla(v11.x + b1s[j0 + 1]);
            Ht[(j0 + 1) * ST + g0 + 3] = tanh_xla(v11.y + b1s[j0 + 1]);
        }
        __syncthreads();

        // --- W2: [16x64]@[64x64], same tile ---
        a00 = a01 = a10 = a11 = 0ull;
        #pragma unroll 8
        for (int k = 0; k < 64; ++k) {
            float4 f4 = *(const float4*)&Ht[k * ST + 4 * q];
            u64 in01 = pack2(f4.x, f4.y), in23 = pack2(f4.z, f4.w);
            float2 w = *(const float2*)&W2t[k * 64 + 2 * c];
            u64 w0 = pack2(w.x, w.x), w1 = pack2(w.y, w.y);
            a00 = fma2(in01, w0, a00); a01 = fma2(in01, w1, a01);
            a10 = fma2(in23, w0, a10); a11 = fma2(in23, w1, a11);
        }
        {
            float2 v00 = unpack2(a00), v01 = unpack2(a01), v10 = unpack2(a10), v11 = unpack2(a11);
            int j0 = 2 * c, g0 = 4 * q;
            // pv[i] lives at (row g0 + (i&1) + 2*(i>>2), col j0 + ((i>>1)&1)).
            // R4 bug: the store loop used the transposed index formula.
            float pv[8] = {
                tanh_xla(v00.x + b2s[j0]),     tanh_xla(v00.y + b2s[j0]),
                tanh_xla(v01.x + b2s[j0 + 1]), tanh_xla(v01.y + b2s[j0 + 1]),
                tanh_xla(v10.x + b2s[j0]),     tanh_xla(v10.y + b2s[j0]),
                tanh_xla(v11.x + b2s[j0 + 1]), tanh_xla(v11.y + b2s[j0 + 1]) };
            #pragma unroll
            for (int i = 0; i < 8; ++i) {
                int j = j0 + ((i >> 1) & 1);
                int g = g0 + (i & 1) + ((i >> 2) << 1);
                Pt[j * ST + g] = pv[i];
                g_P[(((size_t)(base + g)) * T_ + t) * H_ + j] = pv[i];  // deferred heads
            }
        }
        __syncthreads();

        // --- stack-head: 48 sequential dots (order identical to R3) ---
        if (tid < 48) {
            int ee = tid / 3, h = tid - 3 * ee;
            float acc = 0.0f;
            #pragma unroll 8
            for (int k = 0; k < 64; ++k) acc = __fmaf_rn(Pt[k * ST + ee], Wst[k * 3 + h], acc);
            Ls[ee * 4 + h] = acc + bss[h];
        }
        __syncthreads();

        // --- argmax (replicated per-thread) + stack update + next-top select ---
        {
            float l0 = Ls[e * 4], l1 = Ls[e * 4 + 1], l2 = Ls[e * 4 + 2];
            int op = 0; float bst = l0;
            if (l1 > bst) { bst = l1; op = 1; }
            if (l2 > bst) { op = 2; }
            int np = p + op - 1; np = np < 0 ? 0 : np;
            if (seg == 0) {
                ptrS[e] = np;
                if (op == 2) wbits[e * 7 + (p >> 5)] |= (1u << (p & 31));
            }
            if (op == 2) {
                #pragma unroll
                for (int i = 0; i < 8; ++i) {
                    int f = seg + 8 * i;
                    float v = Pt[f * ST + e];                 // p column for element e
                    ostk[(srow + p) * H_ + f] = v;            // push write-through
                    cs[i] = pcp[i];                           // next top = stack[p+1]
                }
            } else if (op == 0) {
                #pragma unroll
                for (int i = 0; i < 8; ++i) cs[i] = pcm[i];   // next top = stack[p-1]
            }                                                  // op==1: keep cs
            if (t + 1 < T_) {
                #pragma unroll
                for (int i = 0; i < 8; ++i) {
                    int f = seg + 8 * i;
                    InT[f * ST + e]        = xs[i];
                    InT[(64 + f) * ST + e] = cs[i];
                }
            }
        }
    }

    if (tid < G_) out[OFF_PTR + base + tid] = (float)ptrS[tid];
    __syncthreads();

    // epilogue: copy never-written stack rows from input
    for (int it = tid; it < G_ * S_; it += NTHR) {
        int ee = it / S_, rr = it - S_ * ee;
        if (!((wbits[ee * 7 + (rr >> 5)] >> (rr & 31)) & 1u)) {
            const float4* src = (const float4*)(stack_in + ((size_t)(base + ee) * S_ + rr) * H_);
            float4* dst = (float4*)(out + OFF_STK + ((size_t)(base + ee) * S_ + rr) * H_);
            #pragma unroll
            for (int v = 0; v < 16; ++v) dst[v] = src[v];
        }
    }
}

// deferred policy/value heads: logits = P @ Wp.T + bp, value = P @ Wv.T + bv
__global__ void __launch_bounds__(256) stacknet_heads(
    const float* __restrict__ Wp, const float* __restrict__ bp,
    const float* __restrict__ Wv, const float* __restrict__ bv,
    float* __restrict__ out)
{
    __shared__ float ws[9 * 64 + 16];
    int tid = threadIdx.x;
    for (int i = tid; i < 512; i += 256) ws[i] = Wp[i];
    if (tid < 64) ws[512 + tid] = Wv[tid];
    if (tid < 8)  ws[576 + tid] = bp[tid];
    if (tid == 8) ws[584] = bv[0];
    __syncthreads();

    size_t r = (size_t)blockIdx.x * 256 + tid;           // r = b*T + t
    const float4* pr = (const float4*)(g_P + r * H_);
    float4 pv[16];
    #pragma unroll
    for (int i = 0; i < 16; ++i) pv[i] = pr[i];

    int b = (int)(r >> 6), t = (int)(r & 63);
    #pragma unroll
    for (int h = 0; h < 9; ++h) {
        float acc = 0.0f;
        #pragma unroll
        for (int k2 = 0; k2 < 16; ++k2) {
            float4 f = pv[k2];
            const float* w = &ws[h * 64 + 4 * k2];
            acc = __fmaf_rn(f.x, w[0], acc);
            acc = __fmaf_rn(f.y, w[1], acc);
            acc = __fmaf_rn(f.z, w[2], acc);
            acc = __fmaf_rn(f.w, w[3], acc);
        }
        acc += ws[576 + h];
        if (h < 8) out[r * A_ + h] = acc;
        else       out[OFF_VAL + (size_t)t * B_ + b] = acc;
    }
}

extern "C" void kernel_launch(void* const* d_in, const int* in_sizes, int n_in,
                              void* d_out, int out_size) {
    (void)in_sizes; (void)n_in; (void)out_size;
    cudaFuncSetAttribute(stacknet_scan, cudaFuncAttributeMaxDynamicSharedMemorySize, SMEM_BYTES);
    const float* x        = (const float*)d_in[0];
    const float* stack_in = (const float*)d_in[1];
    const int*   ptrs     = (const int*)  d_in[2];
    const float* W1 = (const float*)d_in[3];  const float* b1 = (const float*)d_in[4];
    const float* W2 = (const float*)d_in[5];  const float* b2 = (const float*)d_in[6];
    const float* Ws = (const float*)d_in[7];  const float* bs = (const float*)d_in[8];
    const float* Wp = (const float*)d_in[9];  const float* bp = (const float*)d_in[10];
    const float* Wv = (const float*)d_in[11]; const float* bv = (const float*)d_in[12];
    float* out = (float*)d_out;
    stacknet_scan<<<B_ / G_, NTHR, SMEM_BYTES>>>(
        x, stack_in, ptrs, W1, b1, W2, b2, Ws, bs, out);
    stacknet_heads<<<(B_ * T_) / 256, 256>>>(Wp, bp, Wv, bv, out);
}